// round 3
// baseline (speedup 1.0000x reference)
#include <cuda_runtime.h>
#include <cuda_bf16.h>

#define HH      512          // hidden size (floats)
#define H4      128          // hidden size in float4
#define REF_S   256
#define TAR_S   512
#define NB      8            // batch
#define ND      32           // ref docs
#define NREFBLK (NB*ND)      // 256
#define NLAB    5

// flat fp32 output layout (reference tuple order, masks as 0/1 floats)
#define O_TAR_AUG       0        // [8,5,512]   = 20480
#define O_TAR_AUG_MASK  20480    // [8,5]       = 40
#define O_REF_AUG       20520    // [8,32,5,512]= 655360
#define O_REF_AUG_MASK  675880   // [8,32,5]    = 1280
#define O_TARPAPER      677160   // [8,512]     = 4096
#define O_TAR_MASK2     681256   // [8]         = 8
#define O_REFPAPER      681264   // [8,32,512]  = 131072
#define O_REF_MASK2     812336   // [8,32]      = 256
// total 812592

__device__ __forceinline__ void fadd4(float4& a, const float4 b) {
    a.x += b.x; a.y += b.y; a.z += b.z; a.w += b.w;
}

__global__ __launch_bounds__(256, 2)
void em_encoder_kernel(const float* __restrict__ tar_state,
                       const int*   __restrict__ tar_func,
                       const float* __restrict__ ref_state,
                       const int*   __restrict__ ref_func,
                       float*       __restrict__ out)
{
    __shared__ int            sfunc[TAR_S];
    __shared__ unsigned short slist[NLAB][TAR_S];
    __shared__ int            scnt[NLAB];
    __shared__ float4         sbuf[H4][NLAB];   // parity-combine buffer (10KB)

    const int bid = blockIdx.x;
    const int t   = threadIdx.x;          // 0..255
    const int c   = t & 127;              // float4 column
    const int p   = t >> 7;               // sentence parity
    const bool is_ref = (bid < NREFBLK);
    const int S = is_ref ? REF_S : TAR_S;

    const float4* stc;                     // column-c base, stride H4 per sentence
    const int*    fn;
    if (is_ref) {
        stc = reinterpret_cast<const float4*>(ref_state) + (size_t)bid * REF_S * H4 + c;
        fn  = ref_func + bid * REF_S;
    } else {
        const int b = bid - NREFBLK;
        stc = reinterpret_cast<const float4*>(tar_state) + (size_t)b * TAR_S * H4 + c;
        fn  = tar_func + b * TAR_S;
    }

    // stage func into shared
    for (int s = t; s < S; s += 256) sfunc[s] = fn[s];
    __syncthreads();

    // Deterministic warp-ballot compaction: warp w (0..4) builds ascending
    // index list of sentences with label w+1.
    const int wid = t >> 5, lane = t & 31;
    if (wid < NLAB) {
        const int l = wid + 1;
        int base = 0;
        for (int s0 = 0; s0 < S; s0 += 32) {
            const int s = s0 + lane;
            const int f = sfunc[s];
            const unsigned m = __ballot_sync(0xffffffffu, f == l);
            if (f == l)
                slist[wid][base + __popc(m & ((1u << lane) - 1u))] = (unsigned short)s;
            base += __popc(m);
        }
        if (lane == 0) scnt[wid] = base;
    }
    __syncthreads();

    // Hot loop: per label, gather-sum rows. Thread handles list entries with
    // index ≡ p (mod 2): 8 independent LDG.128 in flight -> 4KB/warp.
    float4 acc[NLAB];
    int    cnt[NLAB];

    #pragma unroll
    for (int l = 0; l < NLAB; l++) {
        const int n = scnt[l];
        cnt[l] = n;
        const int np = (n - p + 1) >> 1;          // entries for this parity
        float4 a = make_float4(0.f, 0.f, 0.f, 0.f);
        const unsigned short* lst = slist[l];
        int i = 0;
        for (; i + 8 <= np; i += 8) {
            const int j = 2 * i + p;              // j, j+2, ..., j+14
            float4 v0 = stc[(size_t)lst[j +  0] * H4];
            float4 v1 = stc[(size_t)lst[j +  2] * H4];
            float4 v2 = stc[(size_t)lst[j +  4] * H4];
            float4 v3 = stc[(size_t)lst[j +  6] * H4];
            float4 v4 = stc[(size_t)lst[j +  8] * H4];
            float4 v5 = stc[(size_t)lst[j + 10] * H4];
            float4 v6 = stc[(size_t)lst[j + 12] * H4];
            float4 v7 = stc[(size_t)lst[j + 14] * H4];
            fadd4(v0, v1); fadd4(v2, v3); fadd4(v4, v5); fadd4(v6, v7);
            fadd4(v0, v2); fadd4(v4, v6);
            fadd4(v0, v4);
            fadd4(a, v0);
        }
        for (; i < np; i++) {
            float4 v = stc[(size_t)lst[2 * i + p] * H4];
            fadd4(a, v);
        }
        acc[l] = a;
    }
    const int ctot = cnt[0] + cnt[1] + cnt[2] + cnt[3] + cnt[4];

    // Combine parities through shared
    if (p == 1) {
        #pragma unroll
        for (int l = 0; l < NLAB; l++) sbuf[c][l] = acc[l];
    }
    __syncthreads();

    if (p == 0) {
        float4 tot = make_float4(0.f, 0.f, 0.f, 0.f);
        #pragma unroll
        for (int l = 0; l < NLAB; l++) {
            fadd4(acc[l], sbuf[c][l]);
            fadd4(tot, acc[l]);                    // masked sum == Σ labels 1..5
        }

        float* aug;
        float* paper;
        if (is_ref) {
            aug   = out + O_REF_AUG   + (size_t)bid * NLAB * HH;
            paper = out + O_REFPAPER  + (size_t)bid * HH;
        } else {
            const int b = bid - NREFBLK;
            aug   = out + O_TAR_AUG   + (size_t)b * NLAB * HH;
            paper = out + O_TARPAPER  + (size_t)b * HH;
        }
        #pragma unroll
        for (int l = 0; l < NLAB; l++) {
            const float inv = 1.f / (cnt[l] > 0 ? (float)cnt[l] : 1e11f);
            reinterpret_cast<float4*>(aug + l * HH)[c] =
                make_float4(acc[l].x * inv, acc[l].y * inv,
                            acc[l].z * inv, acc[l].w * inv);
        }
        const float invt = 1.f / (ctot > 0 ? (float)ctot : 1e11f);
        reinterpret_cast<float4*>(paper)[c] =
            make_float4(tot.x * invt, tot.y * invt, tot.z * invt, tot.w * invt);

        if (is_ref) {
            if (t < NLAB) out[O_REF_AUG_MASK + bid * NLAB + t] = (cnt[t] > 0) ? 1.f : 0.f;
            if (t == 0)   out[O_REF_MASK2 + bid] = (ctot > 0) ? 1.f : 0.f;
        } else {
            const int b = bid - NREFBLK;
            if (t < NLAB) out[O_TAR_AUG_MASK + b * NLAB + t] = (cnt[t] > 0) ? 1.f : 0.f;
            if (t == 0)   out[O_TAR_MASK2 + b] = (ctot > 0) ? 1.f : 0.f;
        }
    }
}

extern "C" void kernel_launch(void* const* d_in, const int* in_sizes, int n_in,
                              void* d_out, int out_size) {
    const float* tar_state = (const float*)d_in[0];
    const int*   tar_func  = (const int*)  d_in[1];
    const float* ref_state = (const float*)d_in[2];
    const int*   ref_func  = (const int*)  d_in[3];
    float* out = (float*)d_out;

    em_encoder_kernel<<<NREFBLK + NB, 256>>>(tar_state, tar_func,
                                             ref_state, ref_func, out);
}

// round 8
// speedup vs baseline: 1.1564x; 1.1564x over previous
#include <cuda_runtime.h>
#include <cuda_bf16.h>

#define HH      512          // hidden size (floats)
#define H2      256          // hidden size in float2
#define REF_S   256
#define TAR_S   512
#define NB      8            // batch
#define ND      32           // ref docs
#define NREFBLK (NB*ND)      // 256
#define NLAB    5

// flat fp32 output layout (reference tuple order, masks as 0/1 floats)
#define O_TAR_AUG       0        // [8,5,512]   = 20480
#define O_TAR_AUG_MASK  20480    // [8,5]       = 40
#define O_REF_AUG       20520    // [8,32,5,512]= 655360
#define O_REF_AUG_MASK  675880   // [8,32,5]    = 1280
#define O_TARPAPER      677160   // [8,512]     = 4096
#define O_TAR_MASK2     681256   // [8]         = 8
#define O_REFPAPER      681264   // [8,32,512]  = 131072
#define O_REF_MASK2     812336   // [8,32]      = 256
// total 812592

#define GRP 16               // loads in flight per group (4KB/warp)

__global__ __launch_bounds__(256, 2)
void em_encoder_kernel(const float* __restrict__ tar_state,
                       const int*   __restrict__ tar_func,
                       const float* __restrict__ ref_state,
                       const int*   __restrict__ ref_func,
                       float*       __restrict__ out)
{
    __shared__ int            sfunc[TAR_S];
    __shared__ unsigned short slist[NLAB][TAR_S];   // rows 1KB each, 16B-aligned
    __shared__ int            scnt[NLAB];

    const int bid = blockIdx.x;
    const int t   = threadIdx.x;       // 0..255, owns float2 column t
    const bool is_ref = (bid < NREFBLK);
    const int S = is_ref ? REF_S : TAR_S;

    const float2* st;
    const int*    fn;
    if (is_ref) {
        st = reinterpret_cast<const float2*>(ref_state) + (size_t)bid * REF_S * H2 + t;
        fn = ref_func + bid * REF_S;
    } else {
        const int b = bid - NREFBLK;
        st = reinterpret_cast<const float2*>(tar_state) + (size_t)b * TAR_S * H2 + t;
        fn = tar_func + b * TAR_S;
    }

    // stage func into shared
    for (int s = t; s < S; s += 256) sfunc[s] = fn[s];
    __syncthreads();

    // Warp-ballot compaction: warp w (0..4) builds ascending index list of
    // sentences with label w+1, then pads the list to a multiple of GRP by
    // repeating entry 0 (those loads get weight 0 in the tail group).
    const int wid = t >> 5, lane = t & 31;
    if (wid < NLAB) {
        const int l = wid + 1;
        int base = 0;                          // uniform across lanes
        for (int s0 = 0; s0 < S; s0 += 32) {
            const int s = s0 + lane;
            const int f = sfunc[s];
            const unsigned m = __ballot_sync(0xffffffffu, f == l);
            if (f == l)
                slist[wid][base + __popc(m & ((1u << lane) - 1u))] = (unsigned short)s;
            base += __popc(m);
        }
        __syncwarp();
        const int npad = ((base + GRP - 1) / GRP) * GRP;     // <= S
        const unsigned short first = (base > 0) ? slist[wid][0] : (unsigned short)0;
        for (int i = base + lane; i < npad; i += 32) slist[wid][i] = first;
        if (lane == 0) scnt[wid] = base;
    }
    __syncthreads();

    // Hot loop: per label, gather-sum rows in GRP-deep load groups.
    // Indices fetched as 2x LDS.128 (16 ushorts); 16 LDG.64 issue back-to-back.
    float2 acc[NLAB];
    int    cnt[NLAB];

    #pragma unroll
    for (int l = 0; l < NLAB; l++) {
        const int n    = scnt[l];
        cnt[l] = n;
        const int full = n / GRP;              // fully-valid groups
        const int ngrp = (n + GRP - 1) / GRP;  // total padded groups
        const unsigned short* lst = slist[l];
        float2 a = make_float2(0.f, 0.f);

        for (int g = 0; g < ngrp; g++) {
            const int base16 = g * GRP;
            // vectorized index fetch: 32B aligned (base16*2 is mult of 32)
            const uint4 iA = *reinterpret_cast<const uint4*>(lst + base16);
            const uint4 iB = *reinterpret_cast<const uint4*>(lst + base16 + 8);
            int idx[GRP];
            idx[0]  = (int)(iA.x & 0xffffu); idx[1]  = (int)(iA.x >> 16);
            idx[2]  = (int)(iA.y & 0xffffu); idx[3]  = (int)(iA.y >> 16);
            idx[4]  = (int)(iA.z & 0xffffu); idx[5]  = (int)(iA.z >> 16);
            idx[6]  = (int)(iA.w & 0xffffu); idx[7]  = (int)(iA.w >> 16);
            idx[8]  = (int)(iB.x & 0xffffu); idx[9]  = (int)(iB.x >> 16);
            idx[10] = (int)(iB.y & 0xffffu); idx[11] = (int)(iB.y >> 16);
            idx[12] = (int)(iB.z & 0xffffu); idx[13] = (int)(iB.z >> 16);
            idx[14] = (int)(iB.w & 0xffffu); idx[15] = (int)(iB.w >> 16);

            float2 v[GRP];
            #pragma unroll
            for (int k = 0; k < GRP; k++)
                v[k] = st[idx[k] * H2];

            if (g < full) {
                // fully-valid group: pairwise fold
                #pragma unroll
                for (int k = 0; k < GRP; k += 2) {
                    v[k].x += v[k+1].x; v[k].y += v[k+1].y;
                }
                #pragma unroll
                for (int k = 0; k < GRP; k += 4) {
                    v[k].x += v[k+2].x; v[k].y += v[k+2].y;
                }
                #pragma unroll
                for (int k = 0; k < GRP; k += 8) {
                    v[k].x += v[k+4].x; v[k].y += v[k+4].y;
                }
                a.x += v[0].x + v[8].x;
                a.y += v[0].y + v[8].y;
            } else {
                // padded tail group: weight-0 FMAs on pads
                #pragma unroll
                for (int k = 0; k < GRP; k++) {
                    const float w = (base16 + k < n) ? 1.f : 0.f;
                    a.x = fmaf(w, v[k].x, a.x);
                    a.y = fmaf(w, v[k].y, a.y);
                }
            }
        }
        acc[l] = a;
    }
    const int ctot = cnt[0] + cnt[1] + cnt[2] + cnt[3] + cnt[4];

    float2 tot = make_float2(0.f, 0.f);
    #pragma unroll
    for (int l = 0; l < NLAB; l++) { tot.x += acc[l].x; tot.y += acc[l].y; }

    // epilogue
    float* aug;
    float* paper;
    if (is_ref) {
        aug   = out + O_REF_AUG  + (size_t)bid * NLAB * HH;
        paper = out + O_REFPAPER + (size_t)bid * HH;
    } else {
        const int b = bid - NREFBLK;
        aug   = out + O_TAR_AUG  + (size_t)b * NLAB * HH;
        paper = out + O_TARPAPER + (size_t)b * HH;
    }
    #pragma unroll
    for (int l = 0; l < NLAB; l++) {
        const float inv = 1.f / (cnt[l] > 0 ? (float)cnt[l] : 1e11f);
        reinterpret_cast<float2*>(aug + l * HH)[t] =
            make_float2(acc[l].x * inv, acc[l].y * inv);
    }
    const float invt = 1.f / (ctot > 0 ? (float)ctot : 1e11f);
    reinterpret_cast<float2*>(paper)[t] = make_float2(tot.x * invt, tot.y * invt);

    if (is_ref) {
        if (t < NLAB) out[O_REF_AUG_MASK + bid * NLAB + t] = (cnt[t] > 0) ? 1.f : 0.f;
        if (t == 0)   out[O_REF_MASK2 + bid] = (ctot > 0) ? 1.f : 0.f;
    } else {
        const int b = bid - NREFBLK;
        if (t < NLAB) out[O_TAR_AUG_MASK + b * NLAB + t] = (cnt[t] > 0) ? 1.f : 0.f;
        if (t == 0)   out[O_TAR_MASK2 + b] = (ctot > 0) ? 1.f : 0.f;
    }
}

extern "C" void kernel_launch(void* const* d_in, const int* in_sizes, int n_in,
                              void* d_out, int out_size) {
    const float* tar_state = (const float*)d_in[0];
    const int*   tar_func  = (const int*)  d_in[1];
    const float* ref_state = (const float*)d_in[2];
    const int*   ref_func  = (const int*)  d_in[3];
    float* out = (float*)d_out;

    em_encoder_kernel<<<NREFBLK + NB, 256>>>(tar_state, tar_func,
                                             ref_state, ref_func, out);
}